// round 2
// baseline (speedup 1.0000x reference)
#include <cuda_runtime.h>
#include <cuda_fp16.h>
#include <cstdint>

// ---------------- problem sizes ----------------
static constexpr int M_TOTAL = 32768;   // B*S = 4*8192
static constexpr int K_TOTAL = 1024;    // I
static constexpr int N_TOTAL = 1024;    // O
static constexpr int TILE_M  = 128;
static constexpr int TILE_N  = 128;
static constexpr int TILE_K  = 64;
static constexpr int NUM_KC  = K_TOTAL / TILE_K;        // 16
static constexpr int M_TILES = M_TOTAL / TILE_M;        // 256
static constexpr int N_TILES = N_TOTAL / TILE_N;        // 8
static constexpr int STAGE_BYTES = TILE_M * TILE_K * 2; // 16384 per operand per stage
static constexpr int STAGES  = 4;
static constexpr int SMEM_TOTAL = 2 * STAGES * STAGE_BYTES; // 131072

// ---------------- device scratch (static globals: allowed) ----------------
__device__ __align__(16) __half g_xh[(size_t)M_TOTAL * K_TOTAL]; // 64 MiB f16 x, row-major
__device__ __align__(16) __half g_wh[(size_t)N_TOTAL * K_TOTAL]; // 2 MiB f16 ternary W, row-major
__device__ double g_rowsum[1024];
__device__ float  g_thr;

// ---------------- helpers ----------------
__device__ __forceinline__ uint32_t smem_u32(const void* p) {
    uint32_t a;
    asm("{ .reg .u64 t; cvta.to.shared.u64 t, %1; cvt.u32.u64 %0, t; }" : "=r"(a) : "l"(p));
    return a;
}
// Swizzle<3,4,3>: conflict-free for 128B rows with ldmatrix
__device__ __forceinline__ uint32_t sw128(uint32_t off) { return off ^ ((off >> 3) & 0x70); }

__device__ __forceinline__ void cp_async16(uint32_t smem_addr, const void* gptr) {
    asm volatile("cp.async.cg.shared.global [%0], [%1], 16;"
                 :: "r"(smem_addr), "l"(gptr) : "memory");
}
#define CP_COMMIT() asm volatile("cp.async.commit_group;" ::: "memory")
#define CP_WAIT(n)  asm volatile("cp.async.wait_group %0;" :: "n"(n) : "memory")

__device__ __forceinline__ void ldmatrix_x4(uint32_t* r, uint32_t addr) {
    asm volatile("ldmatrix.sync.aligned.m8n8.x4.shared.b16 {%0,%1,%2,%3}, [%4];"
                 : "=r"(r[0]), "=r"(r[1]), "=r"(r[2]), "=r"(r[3]) : "r"(addr));
}
__device__ __forceinline__ void mma16816(float* d, const uint32_t* a, const uint32_t* b) {
    asm volatile(
        "mma.sync.aligned.m16n8k16.row.col.f32.f16.f16.f32 "
        "{%0,%1,%2,%3}, {%4,%5,%6,%7}, {%8,%9}, {%0,%1,%2,%3};"
        : "+f"(d[0]), "+f"(d[1]), "+f"(d[2]), "+f"(d[3])
        : "r"(a[0]), "r"(a[1]), "r"(a[2]), "r"(a[3]), "r"(b[0]), "r"(b[1]));
}

// ---------------- kernel 0: per-row |W| sums in fp64 (deterministic) ------
__global__ void absrow_kernel(const float* __restrict__ W) {
    __shared__ double sred[256];
    int o = blockIdx.x;
    const float* row = W + (size_t)o * K_TOTAL;
    double s = 0.0;
    for (int k = threadIdx.x; k < K_TOTAL; k += 256) s += (double)fabsf(row[k]);
    sred[threadIdx.x] = s;
    __syncthreads();
    for (int off = 128; off > 0; off >>= 1) {
        if (threadIdx.x < off) sred[threadIdx.x] += sred[threadIdx.x + off];
        __syncthreads();
    }
    if (threadIdx.x == 0) g_rowsum[o] = sred[0];
}

// ---------------- kernel 1: alpha = mean(|W|); threshold = 0.5f*alpha -----
__global__ void alpha_kernel() {
    __shared__ double sred[256];
    double s = 0.0;
    for (int i = threadIdx.x; i < 1024; i += 256) s += g_rowsum[i];
    sred[threadIdx.x] = s;
    __syncthreads();
    for (int off = 128; off > 0; off >>= 1) {
        if (threadIdx.x < off) sred[threadIdx.x] += sred[threadIdx.x + off];
        __syncthreads();
    }
    if (threadIdx.x == 0) {
        float alpha = (float)(sred[0] / ((double)N_TOTAL * (double)K_TOTAL));
        g_thr = alpha * 0.5f;
    }
}

// ---------------- kernel 2: ternarize W -> f16 row-major ------------------
__global__ void ternarize_kernel(const float* __restrict__ W) {
    int idx = blockIdx.x * blockDim.x + threadIdx.x;   // over N*K/8 16B-chunks
    if (idx >= N_TOTAL * K_TOTAL / 8) return;
    const float4* src = (const float4*)W + idx * 2;
    float t = g_thr;
    __half h[8];
    #pragma unroll
    for (int v = 0; v < 2; v++) {
        float4 f = src[v];
        float q[4];
        q[0] = (fabsf(f.x) > t) ? (f.x > 0.f ? 1.f : -1.f) : 0.f;
        q[1] = (fabsf(f.y) > t) ? (f.y > 0.f ? 1.f : -1.f) : 0.f;
        q[2] = (fabsf(f.z) > t) ? (f.z > 0.f ? 1.f : -1.f) : 0.f;
        q[3] = (fabsf(f.w) > t) ? (f.w > 0.f ? 1.f : -1.f) : 0.f;
        #pragma unroll
        for (int j = 0; j < 4; j++) h[v * 4 + j] = __float2half_rn(q[j]);
    }
    *((uint4*)g_wh + idx) = *(const uint4*)h;
}

// ---------------- kernel 3: x fp32 -> f16 row-major -----------------------
__global__ void convx_kernel(const float* __restrict__ x) {
    int idx = blockIdx.x * blockDim.x + threadIdx.x;   // over M*K/8 16B-chunks
    if (idx >= M_TOTAL * K_TOTAL / 8) return;
    const float4* src = (const float4*)x + (size_t)idx * 2;
    float4 f0 = src[0], f1 = src[1];
    __half2 h[4];
    h[0] = __floats2half2_rn(f0.x, f0.y);
    h[1] = __floats2half2_rn(f0.z, f0.w);
    h[2] = __floats2half2_rn(f1.x, f1.y);
    h[3] = __floats2half2_rn(f1.z, f1.w);
    *((uint4*)g_xh + idx) = *(const uint4*)h;
}

// ---------------- kernel 4: f16 mma.sync GEMM, 128x128 tile, K=1024 -------
__global__ void __launch_bounds__(256, 1) gemm_kernel(const float* __restrict__ bias,
                                                      float* __restrict__ out) {
    extern __shared__ char smem[];
    const int tid = threadIdx.x, lane = tid & 31, wid = tid >> 5;
    const int warp_m = wid & 1;        // 2 warps along M (64 rows each)
    const int warp_n = wid >> 1;       // 4 warps along N (32 cols each)
    const int n_tile = blockIdx.x, m_tile = blockIdx.y;

    const uint32_t sA = smem_u32(smem);
    const uint32_t sB = sA + STAGES * STAGE_BYTES;

    const char* gA = (const char*)(g_xh + (size_t)(m_tile * TILE_M) * K_TOTAL);
    const char* gB = (const char*)(g_wh + (size_t)(n_tile * TILE_N) * K_TOTAL);
    const int GROW = K_TOTAL * 2;      // gmem row stride in bytes

    // per-thread cp.async mapping: 4 chunks for A + 4 for B per stage
    int cprow[4], cpc8[4];
    #pragma unroll
    for (int i = 0; i < 4; i++) {
        int linear = tid + i * 256;
        cprow[i] = linear >> 3;        // 0..127
        cpc8[i]  = linear & 7;         // 16B chunk in 128B row
    }

    auto issue_stage = [&](int kc, int s) {
        uint32_t dA = sA + s * STAGE_BYTES, dB = sB + s * STAGE_BYTES;
        const char* srcA = gA + kc * (TILE_K * 2);
        const char* srcB = gB + kc * (TILE_K * 2);
        #pragma unroll
        for (int i = 0; i < 4; i++) {
            uint32_t so = sw128((uint32_t)(cprow[i] * 128 + cpc8[i] * 16));
            size_t go = (size_t)cprow[i] * GROW + cpc8[i] * 16;
            cp_async16(dA + so, srcA + go);
            cp_async16(dB + so, srcB + go);
        }
        CP_COMMIT();
    };

    // prologue: 3 stages in flight
    issue_stage(0, 0);
    issue_stage(1, 1);
    issue_stage(2, 2);

    float acc[4][4][4];
    #pragma unroll
    for (int i = 0; i < 4; i++)
        #pragma unroll
        for (int j = 0; j < 4; j++)
            #pragma unroll
            for (int v = 0; v < 4; v++) acc[i][j][v] = 0.f;

    // ldmatrix lane-address components (constant across k-chunks)
    const int a_row = warp_m * 64 + (lane & 15);          // + m_sub*16
    const int a_kof = (lane >> 4) * 8;                    // + kk*16
    const int b_row = warp_n * 32 + (lane & 7) + ((lane >> 4) << 3);  // + ns2*16
    const int b_kof = ((lane >> 3) & 1) * 8;              // + kk*16

    for (int c = 0; c < NUM_KC; c++) {
        if (c <= 13) CP_WAIT(2);
        else if (c == 14) CP_WAIT(1);
        else CP_WAIT(0);
        __syncthreads();

        if (c < NUM_KC - 3) issue_stage(c + 3, (c + 3) & 3);

        const uint32_t aT = sA + (c & 3) * STAGE_BYTES;
        const uint32_t bT = sB + (c & 3) * STAGE_BYTES;

        #pragma unroll
        for (int kk = 0; kk < 4; kk++) {
            uint32_t af[4][4], bf[2][4];
            #pragma unroll
            for (int ms = 0; ms < 4; ms++)
                ldmatrix_x4(af[ms], aT + sw128((uint32_t)((a_row + ms * 16) * 128 +
                                                          (kk * 16 + a_kof) * 2)));
            #pragma unroll
            for (int ns2 = 0; ns2 < 2; ns2++)
                ldmatrix_x4(bf[ns2], bT + sw128((uint32_t)((b_row + ns2 * 16) * 128 +
                                                           (kk * 16 + b_kof) * 2)));
            #pragma unroll
            for (int ms = 0; ms < 4; ms++)
                #pragma unroll
                for (int ns = 0; ns < 4; ns++)
                    mma16816(acc[ms][ns], af[ms], bf[ns >> 1] + (ns & 1) * 2);
        }
        __syncthreads();
    }

    // ---------------- epilogue: bias add + float2 stores ----------------
    const int colbase = n_tile * TILE_N + warp_n * 32 + 2 * (lane & 3);
    const int rowbase = m_tile * TILE_M + warp_m * 64 + (lane >> 2);
    const float* bp = bias + colbase;
    #pragma unroll
    for (int ns = 0; ns < 4; ns++) {
        float bx = bp[ns * 8], by = bp[ns * 8 + 1];
        #pragma unroll
        for (int ms = 0; ms < 4; ms++) {
            float* p0 = out + (size_t)(rowbase + ms * 16) * N_TOTAL + colbase + ns * 8;
            float2 v0 = {acc[ms][ns][0] + bx, acc[ms][ns][1] + by};
            *(float2*)p0 = v0;
            float* p1 = p0 + 8 * N_TOTAL;
            float2 v1 = {acc[ms][ns][2] + bx, acc[ms][ns][3] + by};
            *(float2*)p1 = v1;
        }
    }
}

// ---------------- launch ----------------
extern "C" void kernel_launch(void* const* d_in, const int* in_sizes, int n_in,
                              void* d_out, int out_size) {
    const float* x = (const float*)d_in[0];  // [4, 8192, 1024]
    const float* W = (const float*)d_in[1];  // [1024, 1024]
    const float* b = (const float*)d_in[2];  // [1024]
    float* out = (float*)d_out;              // [4, 8192, 1024]

    absrow_kernel<<<1024, 256>>>(W);
    alpha_kernel<<<1, 256>>>();
    ternarize_kernel<<<(N_TOTAL * K_TOTAL / 8 + 255) / 256, 256>>>(W);
    convx_kernel<<<(M_TOTAL * K_TOTAL / 8 + 255) / 256, 256>>>(x);

    cudaFuncSetAttribute(gemm_kernel, cudaFuncAttributeMaxDynamicSharedMemorySize, SMEM_TOTAL);
    dim3 grid(N_TILES, M_TILES);  // n fastest: same m-tile rows cluster in a wave -> A reuse in L2
    gemm_kernel<<<grid, 256, SMEM_TOTAL>>>(b, out);
}

// round 3
// speedup vs baseline: 1.2235x; 1.2235x over previous
#include <cuda_runtime.h>
#include <cuda_fp16.h>
#include <cstdint>

// ---------------- problem sizes ----------------
static constexpr int M_TOTAL = 32768;   // B*S = 4*8192
static constexpr int K_TOTAL = 1024;    // I
static constexpr int N_TOTAL = 1024;    // O
static constexpr int TILE_M  = 128;
static constexpr int TILE_N  = 256;
static constexpr int TILE_K  = 64;
static constexpr int NUM_KC  = K_TOTAL / TILE_K;        // 16
static constexpr int M_TILES = M_TOTAL / TILE_M;        // 256
static constexpr int N_TILES = N_TOTAL / TILE_N;        // 4
static constexpr int A_STAGE = TILE_M * TILE_K * 2;     // 16384
static constexpr int B_STAGE = TILE_N * TILE_K * 2;     // 32768
static constexpr int STAGES  = 4;
static constexpr int SMEM_TOTAL = STAGES * (A_STAGE + B_STAGE); // 196608

// ---------------- device scratch ----------------
__device__ __align__(16) __half g_wh[(size_t)N_TOTAL * K_TOTAL]; // 2 MiB ternary W f16 row-major
__device__ double g_rowsum[1024];
__device__ float  g_thr;

// ---------------- helpers ----------------
__device__ __forceinline__ uint32_t smem_u32(const void* p) {
    uint32_t a;
    asm("{ .reg .u64 t; cvta.to.shared.u64 t, %1; cvt.u32.u64 %0, t; }" : "=r"(a) : "l"(p));
    return a;
}
__device__ __forceinline__ uint32_t sw128(uint32_t off) { return off ^ ((off >> 3) & 0x70); }

__device__ __forceinline__ void cp_async16(uint32_t smem_addr, const void* gptr) {
    asm volatile("cp.async.cg.shared.global [%0], [%1], 16;"
                 :: "r"(smem_addr), "l"(gptr) : "memory");
}
#define CP_COMMIT() asm volatile("cp.async.commit_group;" ::: "memory")
#define CP_WAIT(n)  asm volatile("cp.async.wait_group %0;" :: "n"(n) : "memory")

__device__ __forceinline__ void ldmatrix_x4(uint32_t* r, uint32_t addr) {
    asm volatile("ldmatrix.sync.aligned.m8n8.x4.shared.b16 {%0,%1,%2,%3}, [%4];"
                 : "=r"(r[0]), "=r"(r[1]), "=r"(r[2]), "=r"(r[3]) : "r"(addr));
}
__device__ __forceinline__ void mma16816(float* d, const uint32_t* a, const uint32_t* b) {
    asm volatile(
        "mma.sync.aligned.m16n8k16.row.col.f32.f16.f16.f32 "
        "{%0,%1,%2,%3}, {%4,%5,%6,%7}, {%8,%9}, {%0,%1,%2,%3};"
        : "+f"(d[0]), "+f"(d[1]), "+f"(d[2]), "+f"(d[3])
        : "r"(a[0]), "r"(a[1]), "r"(a[2]), "r"(a[3]), "r"(b[0]), "r"(b[1]));
}
__device__ __forceinline__ void sts64(uint32_t addr, uint32_t v0, uint32_t v1) {
    asm volatile("st.shared.v2.b32 [%0], {%1,%2};" :: "r"(addr), "r"(v0), "r"(v1) : "memory");
}
__device__ __forceinline__ uint32_t f2h2(float a, float b) {
    __half2 h = __floats2half2_rn(a, b);
    return *reinterpret_cast<uint32_t*>(&h);
}

// ---------------- kernel 0: per-row |W| sums in fp64 (deterministic) ------
__global__ void absrow_kernel(const float* __restrict__ W) {
    __shared__ double sred[256];
    int o = blockIdx.x;
    const float* row = W + (size_t)o * K_TOTAL;
    double s = 0.0;
    for (int k = threadIdx.x; k < K_TOTAL; k += 256) s += (double)fabsf(row[k]);
    sred[threadIdx.x] = s;
    __syncthreads();
    for (int off = 128; off > 0; off >>= 1) {
        if (threadIdx.x < off) sred[threadIdx.x] += sred[threadIdx.x + off];
        __syncthreads();
    }
    if (threadIdx.x == 0) g_rowsum[o] = sred[0];
}

// ---------------- kernel 1: alpha = mean(|W|); threshold = 0.5f*alpha -----
__global__ void alpha_kernel() {
    __shared__ double sred[256];
    double s = 0.0;
    for (int i = threadIdx.x; i < 1024; i += 256) s += g_rowsum[i];
    sred[threadIdx.x] = s;
    __syncthreads();
    for (int off = 128; off > 0; off >>= 1) {
        if (threadIdx.x < off) sred[threadIdx.x] += sred[threadIdx.x + off];
        __syncthreads();
    }
    if (threadIdx.x == 0) {
        float alpha = (float)(sred[0] / ((double)N_TOTAL * (double)K_TOTAL));
        g_thr = alpha * 0.5f;
    }
}

// ---------------- kernel 2: ternarize W -> f16 row-major ------------------
__global__ void ternarize_kernel(const float* __restrict__ W) {
    int idx = blockIdx.x * blockDim.x + threadIdx.x;   // over N*K/8 16B-out-chunks
    if (idx >= N_TOTAL * K_TOTAL / 8) return;
    const float4* src = (const float4*)W + idx * 2;
    float t = g_thr;
    uint32_t h[4];
    #pragma unroll
    for (int v = 0; v < 2; v++) {
        float4 f = src[v];
        float q0 = (fabsf(f.x) > t) ? (f.x > 0.f ? 1.f : -1.f) : 0.f;
        float q1 = (fabsf(f.y) > t) ? (f.y > 0.f ? 1.f : -1.f) : 0.f;
        float q2 = (fabsf(f.z) > t) ? (f.z > 0.f ? 1.f : -1.f) : 0.f;
        float q3 = (fabsf(f.w) > t) ? (f.w > 0.f ? 1.f : -1.f) : 0.f;
        h[v * 2]     = f2h2(q0, q1);
        h[v * 2 + 1] = f2h2(q2, q3);
    }
    ((uint4*)g_wh)[idx] = make_uint4(h[0], h[1], h[2], h[3]);
}

// ---------------- kernel 3: fused-convert f16 mma.sync GEMM ---------------
// CTA tile 128x256, 8 warps (2M x 4N) of 64x64, 4-stage pipeline.
// A (x) is loaded as fp32 from gmem, converted to f16 in registers, STS'd
// into SW128-swizzled smem. B (ternary W f16) comes in via cp.async.
__global__ void __launch_bounds__(256, 1) gemm_kernel(const float* __restrict__ bias,
                                                      const float* __restrict__ x,
                                                      float* __restrict__ out) {
    extern __shared__ char smem[];
    const int tid = threadIdx.x, lane = tid & 31, wid = tid >> 5;
    const int warp_m = wid & 1;        // 2 warps along M (64 rows)
    const int warp_n = wid >> 1;       // 4 warps along N (64 cols)
    const int n_tile = blockIdx.x, m_tile = blockIdx.y;

    const uint32_t sA = smem_u32(smem);
    const uint32_t sB = sA + STAGES * A_STAGE;

    const float* gX = x + (size_t)(m_tile * TILE_M) * K_TOTAL;       // fp32 A source
    const char*  gB = (const char*)(g_wh + (size_t)(n_tile * TILE_N) * K_TOTAL);
    const int GROWB = K_TOTAL * 2;     // B gmem row stride bytes

    // A staging mapping: 2048 x 16B fp32 chunks per stage, 8 per thread.
    // linear = tid + i*256 ; row = linear>>4 (16 chunks of 16B per 256B fp32 row)
    int a_srow[8], a_c[8];
    // B cp.async mapping: 2048 x 16B chunks per stage, 8 per thread.
    int b_row[8], b_c8[8];
    #pragma unroll
    for (int i = 0; i < 8; i++) {
        int lin = tid + i * 256;
        a_srow[i] = lin >> 4;  a_c[i]  = lin & 15;
        b_row[i]  = lin >> 3;  b_c8[i] = lin & 7;
    }

    auto issue_B = [&](int kc, int s) {
        uint32_t dB = sB + s * B_STAGE;
        const char* srcB = gB + kc * (TILE_K * 2);
        #pragma unroll
        for (int i = 0; i < 8; i++) {
            uint32_t so = sw128((uint32_t)(b_row[i] * 128 + b_c8[i] * 16));
            cp_async16(dB + so, srcB + (size_t)b_row[i] * GROWB + b_c8[i] * 16);
        }
        CP_COMMIT();
    };
    auto ldg_A = [&](int kc, float4* buf) {
        #pragma unroll
        for (int i = 0; i < 8; i++)
            buf[i] = *(const float4*)(gX + (size_t)a_srow[i] * K_TOTAL + kc * TILE_K + a_c[i] * 4);
    };
    auto sts_A = [&](int s, const float4* buf) {
        uint32_t dA = sA + s * A_STAGE;
        #pragma unroll
        for (int i = 0; i < 8; i++) {
            uint32_t so = sw128((uint32_t)(a_srow[i] * 128 + a_c[i] * 8));
            sts64(dA + so, f2h2(buf[i].x, buf[i].y), f2h2(buf[i].z, buf[i].w));
        }
    };

    // prologue: B for stages 0..2, then A (serial)
    issue_B(0, 0); issue_B(1, 1); issue_B(2, 2);
    {
        float4 pbuf[8];
        ldg_A(0, pbuf); sts_A(0, pbuf);
        ldg_A(1, pbuf); sts_A(1, pbuf);
        ldg_A(2, pbuf); sts_A(2, pbuf);
    }

    float acc[4][8][4];
    #pragma unroll
    for (int i = 0; i < 4; i++)
        #pragma unroll
        for (int j = 0; j < 8; j++)
            #pragma unroll
            for (int v = 0; v < 4; v++) acc[i][j][v] = 0.f;

    // ldmatrix lane-address components
    const int a_row = warp_m * 64 + (lane & 15);
    const int a_kof = (lane >> 4) * 8;
    const int b_lrow = warp_n * 64 + (lane & 7) + ((lane >> 4) << 3);
    const int b_kof = ((lane >> 3) & 1) * 8;

    for (int c = 0; c < NUM_KC; c++) {
        if (c <= 13) CP_WAIT(2);
        else if (c == 14) CP_WAIT(1);
        else CP_WAIT(0);
        __syncthreads();

        const int nc = c + 3;
        float4 buf[8];
        if (nc < NUM_KC) {
            ldg_A(nc, buf);              // latency hidden under this chunk's MMAs
            issue_B(nc, nc & 3);
        }

        const uint32_t aT = sA + (c & 3) * A_STAGE;
        const uint32_t bT = sB + (c & 3) * B_STAGE;

        #pragma unroll
        for (int kk = 0; kk < 4; kk++) {
            uint32_t af[4][4], bf[4][4];
            #pragma unroll
            for (int ms = 0; ms < 4; ms++)
                ldmatrix_x4(af[ms], aT + sw128((uint32_t)((a_row + ms * 16) * 128 +
                                                          (kk * 16 + a_kof) * 2)));
            #pragma unroll
            for (int ns2 = 0; ns2 < 4; ns2++)
                ldmatrix_x4(bf[ns2], bT + sw128((uint32_t)((b_lrow + ns2 * 16) * 128 +
                                                           (kk * 16 + b_kof) * 2)));
            #pragma unroll
            for (int ms = 0; ms < 4; ms++)
                #pragma unroll
                for (int ns = 0; ns < 8; ns++)
                    mma16816(acc[ms][ns], af[ms], bf[ns >> 1] + (ns & 1) * 2);
        }

        if (nc < NUM_KC) sts_A(nc & 3, buf);
    }

    // ---------------- epilogue: bias add + float2 stores ----------------
    const int colbase = n_tile * TILE_N + warp_n * 64 + 2 * (lane & 3);
    const int rowbase = m_tile * TILE_M + warp_m * 64 + (lane >> 2);
    #pragma unroll
    for (int ns = 0; ns < 8; ns++) {
        float bx = bias[colbase + ns * 8], by = bias[colbase + ns * 8 + 1];
        #pragma unroll
        for (int ms = 0; ms < 4; ms++) {
            float* p0 = out + (size_t)(rowbase + ms * 16) * N_TOTAL + colbase + ns * 8;
            float2 v0 = {acc[ms][ns][0] + bx, acc[ms][ns][1] + by};
            *(float2*)p0 = v0;
            float* p1 = p0 + 8 * N_TOTAL;
            float2 v1 = {acc[ms][ns][2] + bx, acc[ms][ns][3] + by};
            *(float2*)p1 = v1;
        }
    }
}

// ---------------- launch ----------------
extern "C" void kernel_launch(void* const* d_in, const int* in_sizes, int n_in,
                              void* d_out, int out_size) {
    const float* x = (const float*)d_in[0];  // [4, 8192, 1024]
    const float* W = (const float*)d_in[1];  // [1024, 1024]
    const float* b = (const float*)d_in[2];  // [1024]
    float* out = (float*)d_out;              // [4, 8192, 1024]

    absrow_kernel<<<1024, 256>>>(W);
    alpha_kernel<<<1, 256>>>();
    ternarize_kernel<<<(N_TOTAL * K_TOTAL / 8 + 255) / 256, 256>>>(W);

    cudaFuncSetAttribute(gemm_kernel, cudaFuncAttributeMaxDynamicSharedMemorySize, SMEM_TOTAL);
    dim3 grid(N_TILES, M_TILES);  // n fastest: m-tile rows cluster within a wave -> x reuse in L2
    gemm_kernel<<<grid, 256, SMEM_TOTAL>>>(b, x, out);
}

// round 4
// speedup vs baseline: 1.2293x; 1.0047x over previous
#include <cuda_runtime.h>
#include <cuda_fp16.h>
#include <cstdint>

// ---------------- problem sizes ----------------
static constexpr int M_TOTAL = 32768;   // B*S = 4*8192
static constexpr int K_TOTAL = 1024;    // I
static constexpr int N_TOTAL = 1024;    // O
static constexpr int TILE_M  = 128;
static constexpr int TILE_N  = 256;
static constexpr int TILE_K  = 64;
static constexpr int NUM_KC  = K_TOTAL / TILE_K;        // 16
static constexpr int M_TILES = M_TOTAL / TILE_M;        // 256
static constexpr int N_TILES = N_TOTAL / TILE_N;        // 4
static constexpr int A_STAGE = TILE_M * TILE_K * 2;     // 16384
static constexpr int B_STAGE = TILE_N * TILE_K * 2;     // 32768
static constexpr int STAGES  = 4;
static constexpr int SMEM_TOTAL = STAGES * (A_STAGE + B_STAGE); // 196608

// ---------------- device scratch ----------------
__device__ __align__(16) __half g_wh[(size_t)N_TOTAL * K_TOTAL]; // 2 MiB ternary W f16 row-major
__device__ double g_rowsum[1024];

// ---------------- helpers ----------------
__device__ __forceinline__ uint32_t smem_u32(const void* p) {
    uint32_t a;
    asm("{ .reg .u64 t; cvta.to.shared.u64 t, %1; cvt.u32.u64 %0, t; }" : "=r"(a) : "l"(p));
    return a;
}
__device__ __forceinline__ uint32_t sw128(uint32_t off) { return off ^ ((off >> 3) & 0x70); }

__device__ __forceinline__ void cp_async16(uint32_t smem_addr, const void* gptr) {
    asm volatile("cp.async.cg.shared.global [%0], [%1], 16;"
                 :: "r"(smem_addr), "l"(gptr) : "memory");
}
#define CP_COMMIT() asm volatile("cp.async.commit_group;" ::: "memory")
#define CP_WAIT(n)  asm volatile("cp.async.wait_group %0;" :: "n"(n) : "memory")

__device__ __forceinline__ void ldmatrix_x4(uint32_t* r, uint32_t addr) {
    asm volatile("ldmatrix.sync.aligned.m8n8.x4.shared.b16 {%0,%1,%2,%3}, [%4];"
                 : "=r"(r[0]), "=r"(r[1]), "=r"(r[2]), "=r"(r[3]) : "r"(addr));
}
__device__ __forceinline__ void mma16816(float* d, const uint32_t* a, const uint32_t* b) {
    asm volatile(
        "mma.sync.aligned.m16n8k16.row.col.f32.f16.f16.f32 "
        "{%0,%1,%2,%3}, {%4,%5,%6,%7}, {%8,%9}, {%0,%1,%2,%3};"
        : "+f"(d[0]), "+f"(d[1]), "+f"(d[2]), "+f"(d[3])
        : "r"(a[0]), "r"(a[1]), "r"(a[2]), "r"(a[3]), "r"(b[0]), "r"(b[1]));
}
__device__ __forceinline__ void sts64(uint32_t addr, uint32_t v0, uint32_t v1) {
    asm volatile("st.shared.v2.b32 [%0], {%1,%2};" :: "r"(addr), "r"(v0), "r"(v1) : "memory");
}
__device__ __forceinline__ uint32_t f2h2(float a, float b) {
    __half2 h = __floats2half2_rn(a, b);
    return *reinterpret_cast<uint32_t*>(&h);
}

// ---------------- kernel 0: per-row |W| sums in fp64 (deterministic) ------
__global__ void absrow_kernel(const float* __restrict__ W) {
    __shared__ double sred[256];
    int o = blockIdx.x;
    const float* row = W + (size_t)o * K_TOTAL;
    double s = 0.0;
    for (int k = threadIdx.x; k < K_TOTAL; k += 256) s += (double)fabsf(row[k]);
    sred[threadIdx.x] = s;
    __syncthreads();
    for (int off = 128; off > 0; off >>= 1) {
        if (threadIdx.x < off) sred[threadIdx.x] += sred[threadIdx.x + off];
        __syncthreads();
    }
    if (threadIdx.x == 0) g_rowsum[o] = sred[0];
}

// ---------------- kernel 1: alpha (recomputed per block, deterministic)
//                  + ternarize W -> f16 row-major ---------------------------
__global__ void ternarize_kernel(const float* __restrict__ W) {
    __shared__ double sred[256];
    __shared__ float s_thr;
    // every block computes the identical fp64 tree reduction -> same alpha
    {
        double s = 0.0;
        for (int i = threadIdx.x; i < 1024; i += 256) s += g_rowsum[i];
        sred[threadIdx.x] = s;
        __syncthreads();
        for (int off = 128; off > 0; off >>= 1) {
            if (threadIdx.x < off) sred[threadIdx.x] += sred[threadIdx.x + off];
            __syncthreads();
        }
        if (threadIdx.x == 0) {
            float alpha = (float)(sred[0] / ((double)N_TOTAL * (double)K_TOTAL));
            s_thr = alpha * 0.5f;
        }
        __syncthreads();
    }
    float t = s_thr;
    int idx = blockIdx.x * blockDim.x + threadIdx.x;   // over N*K/8 16B-out-chunks
    if (idx >= N_TOTAL * K_TOTAL / 8) return;
    const float4* src = (const float4*)W + idx * 2;
    uint32_t h[4];
    #pragma unroll
    for (int v = 0; v < 2; v++) {
        float4 f = src[v];
        float q0 = (fabsf(f.x) > t) ? (f.x > 0.f ? 1.f : -1.f) : 0.f;
        float q1 = (fabsf(f.y) > t) ? (f.y > 0.f ? 1.f : -1.f) : 0.f;
        float q2 = (fabsf(f.z) > t) ? (f.z > 0.f ? 1.f : -1.f) : 0.f;
        float q3 = (fabsf(f.w) > t) ? (f.w > 0.f ? 1.f : -1.f) : 0.f;
        h[v * 2]     = f2h2(q0, q1);
        h[v * 2 + 1] = f2h2(q2, q3);
    }
    ((uint4*)g_wh)[idx] = make_uint4(h[0], h[1], h[2], h[3]);
}

// ---------------- kernel 2: fused-convert f16 mma.sync GEMM ---------------
// CTA tile 128x256, 8 warps (2M x 4N) of 64x64, 4-stage pipeline.
// Software-pipelined fragments: B double-buffered across kk, A across ms.
__global__ void __launch_bounds__(256, 1) gemm_kernel(const float* __restrict__ bias,
                                                      const float* __restrict__ x,
                                                      float* __restrict__ out) {
    extern __shared__ char smem[];
    const int tid = threadIdx.x, lane = tid & 31, wid = tid >> 5;
    const int warp_m = wid & 1;        // 2 warps along M (64 rows)
    const int warp_n = wid >> 1;       // 4 warps along N (64 cols)
    const int n_tile = blockIdx.x, m_tile = blockIdx.y;

    const uint32_t sA = smem_u32(smem);
    const uint32_t sB = sA + STAGES * A_STAGE;

    // ---- affine producer mappings (no index arrays) ----
    // A: thread handles 16B fp32 chunk (a_r0 + 16*i, a_c), i = 0..7
    const int a_c  = tid & 15;
    const int a_r0 = tid >> 4;
    const uint32_t a_smem0 = sw128((uint32_t)(a_r0 * 128 + a_c * 8)); // +i*2048 (bits>=11: swizzle-safe)
    const float* gA0 = x + (size_t)(m_tile * TILE_M + a_r0) * K_TOTAL + a_c * 4;
    // B: thread handles 16B f16 chunk (b_r0 + 32*i, b_c8), i = 0..7
    const int b_c8 = tid & 7;
    const int b_r0 = tid >> 3;
    const uint32_t b_smem0 = sw128((uint32_t)(b_r0 * 128 + b_c8 * 16)); // +i*4096 (swizzle-safe)
    const char* gB0 = (const char*)(g_wh + (size_t)(n_tile * TILE_N + b_r0) * K_TOTAL) + b_c8 * 16;
    const int GROWB = K_TOTAL * 2;

    auto issue_B = [&](int kc, int s) {
        uint32_t dB = sB + s * B_STAGE + b_smem0;
        const char* srcB = gB0 + kc * (TILE_K * 2);
        #pragma unroll
        for (int i = 0; i < 8; i++)
            cp_async16(dB + i * 4096, srcB + (size_t)i * 32 * GROWB);
        CP_COMMIT();
    };
    auto ldg_A = [&](int kc, float4* buf) {
        const float* srcA = gA0 + kc * TILE_K;
        #pragma unroll
        for (int i = 0; i < 8; i++)
            buf[i] = *(const float4*)(srcA + (size_t)i * 16 * K_TOTAL);
    };
    auto sts_A = [&](int s, const float4* buf) {
        uint32_t dA = sA + s * A_STAGE + a_smem0;
        #pragma unroll
        for (int i = 0; i < 8; i++)
            sts64(dA + i * 2048, f2h2(buf[i].x, buf[i].y), f2h2(buf[i].z, buf[i].w));
    };

    // prologue: B for stages 0..2, then A (serial)
    issue_B(0, 0); issue_B(1, 1); issue_B(2, 2);
    {
        float4 pbuf[8];
        ldg_A(0, pbuf); sts_A(0, pbuf);
        ldg_A(1, pbuf); sts_A(1, pbuf);
        ldg_A(2, pbuf); sts_A(2, pbuf);
    }

    float acc[4][8][4];
    #pragma unroll
    for (int i = 0; i < 4; i++)
        #pragma unroll
        for (int j = 0; j < 8; j++)
            #pragma unroll
            for (int v = 0; v < 4; v++) acc[i][j][v] = 0.f;

    // ldmatrix lane-address components
    const int a_row = warp_m * 64 + (lane & 15);
    const int a_kof = (lane >> 4) * 8;
    const int b_lrow = warp_n * 64 + (lane & 7) + ((lane >> 4) << 3);
    const int b_kof = ((lane >> 3) & 1) * 8;

    uint32_t bf[2][4][4];   // double-buffered across kk
    uint32_t af[2][4];      // double-buffered across ms

    for (int c = 0; c < NUM_KC; c++) {
        if (c <= 13) CP_WAIT(2);
        else if (c == 14) CP_WAIT(1);
        else CP_WAIT(0);
        __syncthreads();

        const int nc = c + 3;
        float4 buf[8];
        if (nc < NUM_KC) {
            ldg_A(nc, buf);              // DRAM latency hides under this chunk's MMAs
            issue_B(nc, nc & 3);
        }

        const uint32_t aT = sA + (c & 3) * A_STAGE;
        const uint32_t bT = sB + (c & 3) * B_STAGE;

        // preload kk=0 B fragments and ms=0 A fragment
        #pragma unroll
        for (int ns2 = 0; ns2 < 4; ns2++)
            ldmatrix_x4(bf[0][ns2], bT + sw128((uint32_t)((b_lrow + ns2 * 16) * 128 + b_kof * 2)));
        ldmatrix_x4(af[0], aT + sw128((uint32_t)(a_row * 128 + a_kof * 2)));

        #pragma unroll
        for (int kk = 0; kk < 4; kk++) {
            #pragma unroll
            for (int ms = 0; ms < 4; ms++) {
                // prefetch next A fragment (next ms, or ms=0 of next kk)
                if (ms < 3)
                    ldmatrix_x4(af[(ms + 1) & 1],
                                aT + sw128((uint32_t)((a_row + (ms + 1) * 16) * 128 +
                                                      (kk * 16 + a_kof) * 2)));
                else if (kk < 3)
                    ldmatrix_x4(af[0],
                                aT + sw128((uint32_t)(a_row * 128 +
                                                      ((kk + 1) * 16 + a_kof) * 2)));
                // prefetch one B fragment of next kk per ms iteration
                if (kk < 3)
                    ldmatrix_x4(bf[(kk + 1) & 1][ms],
                                bT + sw128((uint32_t)((b_lrow + ms * 16) * 128 +
                                                      ((kk + 1) * 16 + b_kof) * 2)));
                #pragma unroll
                for (int ns = 0; ns < 8; ns++)
                    mma16816(acc[ms][ns], af[ms & 1], bf[kk & 1][ns >> 1] + (ns & 1) * 2);
            }
        }

        if (nc < NUM_KC) sts_A(nc & 3, buf);
    }

    // ---------------- epilogue: bias add + float2 stores ----------------
    const int colbase = n_tile * TILE_N + warp_n * 64 + 2 * (lane & 3);
    const int rowbase = m_tile * TILE_M + warp_m * 64 + (lane >> 2);
    #pragma unroll
    for (int ns = 0; ns < 8; ns++) {
        float bx = bias[colbase + ns * 8], by = bias[colbase + ns * 8 + 1];
        #pragma unroll
        for (int ms = 0; ms < 4; ms++) {
            float* p0 = out + (size_t)(rowbase + ms * 16) * N_TOTAL + colbase + ns * 8;
            float2 v0 = {acc[ms][ns][0] + bx, acc[ms][ns][1] + by};
            *(float2*)p0 = v0;
            float* p1 = p0 + 8 * N_TOTAL;
            float2 v1 = {acc[ms][ns][2] + bx, acc[ms][ns][3] + by};
            *(float2*)p1 = v1;
        }
    }
}

// ---------------- launch ----------------
extern "C" void kernel_launch(void* const* d_in, const int* in_sizes, int n_in,
                              void* d_out, int out_size) {
    const float* x = (const float*)d_in[0];  // [4, 8192, 1024]
    const float* W = (const float*)d_in[1];  // [1024, 1024]
    const float* b = (const float*)d_in[2];  // [1024]
    float* out = (float*)d_out;              // [4, 8192, 1024]

    absrow_kernel<<<1024, 256>>>(W);
    ternarize_kernel<<<(N_TOTAL * K_TOTAL / 8 + 255) / 256, 256>>>(W);

    cudaFuncSetAttribute(gemm_kernel, cudaFuncAttributeMaxDynamicSharedMemorySize, SMEM_TOTAL);
    dim3 grid(N_TILES, M_TILES);  // n fastest: m-tile rows cluster within a wave -> x reuse in L2
    gemm_kernel<<<grid, 256, SMEM_TOTAL>>>(b, x, out);
}